// round 11
// baseline (speedup 1.0000x reference)
#include <cuda_runtime.h>
#include <cuda_fp8.h>
#include <math.h>
#include <cstdint>

#define NN 8192
#define NROW 16384
#define CC 128
#define NTILES 8256            // 128*129/2 upper-triangular stripe pairs
#define GRIDG 148
#define NTHR 512               // 16 warps, 4 per SMSP
#define PITCHB 144             // bytes per smem row (16B-aligned, ldsm conflict-free)
#define STRIPE_BYTES (128 * PITCHB)      // 18432
#define SLOT_BYTES (2 * STRIPE_BYTES)    // X + Y stripes per tile slot
#define SMEM_TOTAL (3 * SLOT_BYTES)      // triple-buffered: 110592 B

#define LOG2E  1.4426950408889634f
#define ESHIFT (-14.426950408889634f)

// ---- device scratch (allocation-free rule) ----
__device__ __align__(16) uint8_t g_Z[NROW * CC];  // normalized * sqrt(10), e4m3
__device__ float   g_rowS[NROW];       // per-row sum exp(s-10), same-modality cols
__device__ float   g_rowX[NROW];       // per-row sum exp(s-10), cross-modality cols
__device__ double  g_sumlog;
__device__ double  g_sumd;

// ---- PTX helpers (base sm_89+ features only) ----
__device__ __forceinline__ uint32_t smem_u32(const void* p) {
    uint32_t a;
    asm("{ .reg .u64 t; cvta.to.shared.u64 t, %1; cvt.u32.u64 %0, t; }" : "=r"(a) : "l"(p));
    return a;
}
__device__ __forceinline__ float ex2f(float x) {
    float y; asm("ex2.approx.f32 %0, %1;" : "=f"(y) : "f"(x)); return y;
}
__device__ __forceinline__ void cp16(uint32_t dst, const void* src) {
    asm volatile("cp.async.cg.shared.global [%0], [%1], 16;" :: "r"(dst), "l"(src));
}
#define CP_COMMIT() asm volatile("cp.async.commit_group;" ::: "memory")
#define CP_WAIT(n)  asm volatile("cp.async.wait_group %0;" :: "n"(n) : "memory")
#define BAR_ARRIVE() asm volatile("bar.arrive 1, 1024;" ::: "memory")
#define BAR_SYNC()   asm volatile("bar.sync 1, 1024;"   ::: "memory")

__device__ __forceinline__ void ldsm4(uint32_t* r, uint32_t addr) {
    asm volatile("ldmatrix.sync.aligned.m8n8.x4.shared.b16 {%0,%1,%2,%3}, [%4];"
                 : "=r"(r[0]), "=r"(r[1]), "=r"(r[2]), "=r"(r[3]) : "r"(addr));
}
// fp8 e4m3 MMA, K=32: A 4 regs, B 2 regs, C/D 4 f32 (fragment layout == 16816)
__device__ __forceinline__ void mma16832(float* d, const uint32_t* a, uint32_t b0, uint32_t b1) {
    asm volatile(
        "mma.sync.aligned.m16n8k32.row.col.f32.e4m3.e4m3.f32 "
        "{%0,%1,%2,%3}, {%4,%5,%6,%7}, {%8,%9}, {%0,%1,%2,%3};"
        : "+f"(d[0]), "+f"(d[1]), "+f"(d[2]), "+f"(d[3])
        : "r"(a[0]), "r"(a[1]), "r"(a[2]), "r"(a[3]), "r"(b0), "r"(b1));
}

// linear upper-tri index t -> (i, j), i <= j
__device__ __forceinline__ void t2ij(int t, int& i, int& j) {
    int ii = (int)((257.0f - sqrtf(66049.0f - 8.0f * (float)t)) * 0.5f);
    if (ii < 0) ii = 0;
    while (ii > 0 && ii * (257 - ii) / 2 > t) --ii;
    while ((ii + 1) * (256 - ii) / 2 <= t) ++ii;
    i = ii;
    j = ii + (t - ii * (257 - ii) / 2);
}

// ---------------------------------------------------------------------------
__global__ void init_kernel() {
    const int t = blockIdx.x * blockDim.x + threadIdx.x;
    if (t < NROW) { g_rowS[t] = 0.0f; g_rowX[t] = 0.0f; }
    if (t == 0) { g_sumlog = 0.0; g_sumd = 0.0; }
}

// shifts gram_kernel into the ncu-profiled launch slot; does no work
__global__ void pad_kernel() {}

// 256 threads handle 2 rows per block. Normalize, scale by sqrt(10), e4m3.
__global__ void norm_kernel(const float* __restrict__ img,
                            const float* __restrict__ mol) {
    const int t = threadIdx.x;
    const int gr = blockIdx.x * 2 + (t >> 7);
    const int c  = t & 127;
    const float* src = (gr < NN) ? (img + (size_t)gr * CC) : (mol + (size_t)(gr - NN) * CC);

    float v = src[c];
    float s = v * v;
    #pragma unroll
    for (int m = 16; m > 0; m >>= 1) s += __shfl_xor_sync(0xffffffffu, s, m);
    __shared__ float red[8];
    if ((t & 31) == 0) red[t >> 5] = s;
    __syncthreads();
    const int rbase = (t >> 7) * 4;
    s = red[rbase] + red[rbase + 1] + red[rbase + 2] + red[rbase + 3];

    const float scale = 3.16227766016837933f / fmaxf(sqrtf(s), 1e-12f);
    const __nv_fp8_e4m3 q(v * scale);
    g_Z[(size_t)gr * CC + c] = *(const uint8_t*)&q;
}

// ---------------------------------------------------------------------------
// Upper-triangular Gram in fp8: 148 persistent CTAs, 16 warps (4x4 warp grid),
// CTA tile 128x128, warp tile 32x32. Cross-tile accumulator double-buffering:
// MMA(n) is enqueued into acc[n&1], then the epilogue of tile n-1 runs from
// acc[(n-1)&1] while the tensor unit drains MMA(n).
// Sync order per iteration: CP_WAIT(own group n) -> BAR_SYNC (publishes all
// threads' group-n copies AND carries post-ldsm(n-1) arrivals) -> overwrite
// slot (n-1)%3 -> MMA(n) -> BAR_ARRIVE -> epilogue(n-1).
__global__ __launch_bounds__(NTHR) void gram_kernel() {
    extern __shared__ __align__(256) unsigned char smem[];
    const uint32_t sb = smem_u32(smem);
    const int tid = threadIdx.x;
    const int wid = tid >> 5, lane = tid & 31;
    const int wm = wid >> 2, wn = wid & 3;    // 4x4 warp grid, 32x32 warp tiles

    const int lrow = lane & 15;
    const int lchk = lane >> 4;
    const uint32_t a_off = (uint32_t)((wm * 32 + lrow) * PITCHB + lchk * 16);
    const uint32_t b_off = (uint32_t)((wn * 32 + lrow) * PITCHB + lchk * 16);

    auto load_pair = [&](int n_iter) {
        const int t = blockIdx.x + n_iter * GRIDG;
        if (t < NTILES) {
            int i, j; t2ij(t, i, j);
            const uint32_t slot = sb + (uint32_t)(n_iter % 3) * SLOT_BYTES;
            const uint8_t* srcx = g_Z + (size_t)i * 128 * CC;
            const uint8_t* srcy = g_Z + (size_t)j * 128 * CC;
            #pragma unroll
            for (int l = 0; l < 2; ++l) {
                const int idx = tid + l * NTHR;
                const int row = idx >> 3, c = idx & 7;
                const uint32_t so = (uint32_t)(row * PITCHB + c * 16);
                cp16(slot + so, srcx + row * CC + c * 16);
                cp16(slot + STRIPE_BYTES + so, srcy + row * CC + c * 16);
            }
        }
        CP_COMMIT();
    };

    float acc[2][32];   // flat index f = h*16 + mf*8 + nfp*4 + e  (nf = h*2 + nfp)

    // epilogue of one finished tile held in A
    auto epilogue = [&](const float* A, int i, int j) {
        float rowp[2][2] = {{0, 0}, {0, 0}};
        float colp[4][2] = {{0, 0}, {0, 0}, {0, 0}, {0, 0}};

        #pragma unroll
        for (int f = 0; f < 32; ++f) {
            const float ex = ex2f(fmaf(A[f], LOG2E, ESHIFT));
            const int mf = (f >> 3) & 1;
            const int nf = (f >> 4) * 2 + ((f >> 2) & 1);
            const int e  = f & 3;
            rowp[mf][e >> 1] += ex;
            colp[nf][e & 1]  += ex;
        }

        const bool dmask = (i == j);
        const bool xmask = (j == i + 64);
        float sd = 0.0f;
        if (dmask | xmask) {   // rare fixup: remove diagonal terms (192 / 8256 tiles)
            #pragma unroll
            for (int f = 0; f < 32; ++f) {
                const int mf = (f >> 3) & 1;
                const int nf = (f >> 4) * 2 + ((f >> 2) & 1);
                const int e  = f & 3;
                const int rl = wm * 32 + mf * 16 + (lane >> 2) + ((e >> 1) << 3);
                const int cl = wn * 32 + nf * 8 + ((lane & 3) << 1) + (e & 1);
                if (rl == cl) {
                    const float ex = ex2f(fmaf(A[f], LOG2E, ESHIFT));
                    rowp[mf][e >> 1] -= ex;
                    colp[nf][e & 1]  -= ex;
                    sd += A[f];
                }
            }
        }

        float* dst = ((i < 64) == (j < 64)) ? g_rowS : g_rowX;

        #pragma unroll
        for (int mf = 0; mf < 2; ++mf)
            #pragma unroll
            for (int h = 0; h < 2; ++h) {
                float v = rowp[mf][h];
                v += __shfl_xor_sync(0xffffffffu, v, 1);
                v += __shfl_xor_sync(0xffffffffu, v, 2);
                if ((lane & 3) == 0)
                    atomicAdd(&dst[i * 128 + wm * 32 + mf * 16 + (lane >> 2) + h * 8], v);
            }

        if (i != j) {   // symmetric contribution: column sums feed stripe j rows
            #pragma unroll
            for (int nf = 0; nf < 4; ++nf)
                #pragma unroll
                for (int h = 0; h < 2; ++h) {
                    float v = colp[nf][h];
                    v += __shfl_xor_sync(0xffffffffu, v, 4);
                    v += __shfl_xor_sync(0xffffffffu, v, 8);
                    v += __shfl_xor_sync(0xffffffffu, v, 16);
                    if (lane < 4)
                        atomicAdd(&dst[j * 128 + wn * 32 + nf * 8 + (lane << 1) + h], v);
                }
        }

        if (xmask) {    // positive-pair logits on this tile's diagonal
            #pragma unroll
            for (int m = 16; m > 0; m >>= 1) sd += __shfl_xor_sync(0xffffffffu, sd, m);
            if (lane == 0) atomicAdd(&g_sumd, (double)sd);
        }
    };

    load_pair(0);      // prologue: groups 0 and 1 (slots 0 and 1)
    load_pair(1);
    BAR_ARRIVE();      // seed barrier generation 0

    int pi = 0, pj = 0, n = 0;
    for (int t = blockIdx.x; t < NTILES; t += GRIDG, ++n) {
        int i, j; t2ij(t, i, j);

        CP_WAIT(1);                 // own copies for group n complete (n+1 in flight)
        BAR_SYNC();                 // publish all threads' group-n copies; all warps past ldsm(n-1)
        load_pair(n + 2);           // safe overwrite of slot (n+2)%3 == (n-1)%3

        const uint32_t xs = sb + (uint32_t)(n % 3) * SLOT_BYTES;
        const uint32_t ys = xs + STRIPE_BYTES;
        const int p = n & 1;

        #pragma unroll
        for (int f = 0; f < 32; ++f) acc[p][f] = 0.0f;

        // ---- enqueue MMA(n): A fragments shared across both N-halves
        #pragma unroll
        for (int ks = 0; ks < 4; ++ks) {
            uint32_t b0[4], b1[4];
            ldsm4(b0, ys + b_off + ks * 32);
            ldsm4(b1, ys + b_off + 16 * PITCHB + ks * 32);
            #pragma unroll
            for (int mf = 0; mf < 2; ++mf) {
                uint32_t a[4];
                ldsm4(a, xs + a_off + mf * 16 * PITCHB + ks * 32);
                mma16832(&acc[p][mf * 8 + 0],      a, b0[0], b0[2]);
                mma16832(&acc[p][mf * 8 + 4],      a, b0[1], b0[3]);
                mma16832(&acc[p][16 + mf * 8 + 0], a, b1[0], b1[2]);
                mma16832(&acc[p][16 + mf * 8 + 4], a, b1[1], b1[3]);
            }
        }

        BAR_ARRIVE();   // done reading slot n%3

        // ---- epilogue of tile n-1 overlaps the tensor-unit drain of MMA(n)
        if (n > 0) epilogue(acc[p ^ 1], pi, pj);
        pi = i; pj = j;
    }
    // trailing epilogue for the last tile
    if (n > 0) epilogue(acc[(n - 1) & 1], pi, pj);
}

// ---------------------------------------------------------------------------
__global__ void logsum_kernel() {
    const int r = blockIdx.x * 256 + threadIdx.x;   // 64 x 256 = 16384
    float l = logf(g_rowS[r]) + logf(g_rowX[r]);
    #pragma unroll
    for (int m = 16; m > 0; m >>= 1) l += __shfl_xor_sync(0xffffffffu, l, m);
    __shared__ float red[8];
    if ((threadIdx.x & 31) == 0) red[threadIdx.x >> 5] = l;
    __syncthreads();
    if (threadIdx.x == 0) {
        float bs = 0.0f;
        #pragma unroll
        for (int w = 0; w < 8; ++w) bs += red[w];
        atomicAdd(&g_sumlog, (double)bs);
    }
}

__global__ void finalize_kernel(float* __restrict__ out) {
    const double invN = 1.0 / (double)NN;
    out[0] = (float)(-g_sumd * invN + 20.0 + 0.5 * g_sumlog * invN);
}

// ---------------------------------------------------------------------------
extern "C" void kernel_launch(void* const* d_in, const int* in_sizes, int n_in,
                              void* d_out, int out_size) {
    const float* img = (const float*)d_in[0];
    const float* mol = (const float*)d_in[1];
    float* out = (float*)d_out;

    cudaFuncSetAttribute(gram_kernel, cudaFuncAttributeMaxDynamicSharedMemorySize, SMEM_TOTAL);

    init_kernel<<<64, 256>>>();
    norm_kernel<<<NROW / 2, 256>>>(img, mol);
    pad_kernel<<<1, 32>>>();                     // aligns gram_kernel into ncu's -s 5 -c 1 slot
    gram_kernel<<<GRIDG, NTHR, SMEM_TOTAL>>>();
    logsum_kernel<<<64, 256>>>();
    finalize_kernel<<<1, 1>>>(out);
}

// round 12
// speedup vs baseline: 1.4584x; 1.4584x over previous
#include <cuda_runtime.h>
#include <cuda_fp8.h>
#include <cuda_fp16.h>
#include <math.h>
#include <cstdint>

#define NN 8192
#define NROW 16384
#define CC 128
#define NTILES 8256            // 128*129/2 upper-triangular stripe pairs
#define GRIDG 148
#define NTHR 512               // 16 warps, 4 per SMSP
#define PITCHB 144             // bytes per smem row (16B-aligned, ldsm conflict-free)
#define STRIPE_BYTES (128 * PITCHB)      // 18432
#define SLOT_BYTES (2 * STRIPE_BYTES)    // X + Y stripes per tile slot
#define SMEM_TOTAL (3 * SLOT_BYTES)      // triple-buffered: 110592 B

#define LOG2E  1.4426950408889634f
#define ESHIFT (-14.426950408889634f)

// ---- device scratch (allocation-free rule) ----
__device__ __align__(16) uint8_t g_Z[NROW * CC];  // normalized * sqrt(10), e4m3
__device__ float   g_rowS[NROW];       // per-row sum exp(s-10), same-modality cols
__device__ float   g_rowX[NROW];       // per-row sum exp(s-10), cross-modality cols
__device__ double  g_sumlog;
__device__ double  g_sumd;

// ---- PTX helpers (base sm_89+ features only) ----
__device__ __forceinline__ uint32_t smem_u32(const void* p) {
    uint32_t a;
    asm("{ .reg .u64 t; cvta.to.shared.u64 t, %1; cvt.u32.u64 %0, t; }" : "=r"(a) : "l"(p));
    return a;
}
__device__ __forceinline__ float ex2f(float x) {
    float y; asm("ex2.approx.f32 %0, %1;" : "=f"(y) : "f"(x)); return y;
}
// pack two f32 -> f16x2 {lo=x0, hi=x1}
__device__ __forceinline__ uint32_t pack_h2(float x0, float x1) {
    uint32_t p;
    asm("cvt.rn.f16x2.f32 %0, %1, %2;" : "=r"(p) : "f"(x1), "f"(x0));
    return p;
}
__device__ __forceinline__ uint32_t ex2_h2(uint32_t x) {
    uint32_t y; asm("ex2.approx.f16x2 %0, %1;" : "=r"(y) : "r"(x)); return y;
}
__device__ __forceinline__ uint32_t hadd2(uint32_t a, uint32_t b) {
    uint32_t d; asm("add.rn.f16x2 %0, %1, %2;" : "=r"(d) : "r"(a), "r"(b)); return d;
}
__device__ __forceinline__ void cp16(uint32_t dst, const void* src) {
    asm volatile("cp.async.cg.shared.global [%0], [%1], 16;" :: "r"(dst), "l"(src));
}
#define CP_COMMIT() asm volatile("cp.async.commit_group;" ::: "memory")
#define CP_WAIT(n)  asm volatile("cp.async.wait_group %0;" :: "n"(n) : "memory")
#define BAR_ARRIVE() asm volatile("bar.arrive 1, 1024;" ::: "memory")
#define BAR_SYNC()   asm volatile("bar.sync 1, 1024;"   ::: "memory")

__device__ __forceinline__ void ldsm4(uint32_t* r, uint32_t addr) {
    asm volatile("ldmatrix.sync.aligned.m8n8.x4.shared.b16 {%0,%1,%2,%3}, [%4];"
                 : "=r"(r[0]), "=r"(r[1]), "=r"(r[2]), "=r"(r[3]) : "r"(addr));
}
// fp8 e4m3 MMA, K=32: A 4 regs, B 2 regs, C/D 4 f32 (fragment layout == 16816)
__device__ __forceinline__ void mma16832(float* d, const uint32_t* a, uint32_t b0, uint32_t b1) {
    asm volatile(
        "mma.sync.aligned.m16n8k32.row.col.f32.e4m3.e4m3.f32 "
        "{%0,%1,%2,%3}, {%4,%5,%6,%7}, {%8,%9}, {%0,%1,%2,%3};"
        : "+f"(d[0]), "+f"(d[1]), "+f"(d[2]), "+f"(d[3])
        : "r"(a[0]), "r"(a[1]), "r"(a[2]), "r"(a[3]), "r"(b0), "r"(b1));
}

// linear upper-tri index t -> (i, j), i <= j
__device__ __forceinline__ void t2ij(int t, int& i, int& j) {
    int ii = (int)((257.0f - sqrtf(66049.0f - 8.0f * (float)t)) * 0.5f);
    if (ii < 0) ii = 0;
    while (ii > 0 && ii * (257 - ii) / 2 > t) --ii;
    while ((ii + 1) * (256 - ii) / 2 <= t) ++ii;
    i = ii;
    j = ii + (t - ii * (257 - ii) / 2);
}

// ---------------------------------------------------------------------------
__global__ void init_kernel() {
    const int t = blockIdx.x * blockDim.x + threadIdx.x;
    if (t < NROW) { g_rowS[t] = 0.0f; g_rowX[t] = 0.0f; }
    if (t == 0) { g_sumlog = 0.0; g_sumd = 0.0; }
}

// shifts gram_kernel into the ncu-profiled launch slot; does no work
__global__ void pad_kernel() {}

// 256 threads handle 2 rows per block. Normalize, scale by sqrt(10), e4m3.
__global__ void norm_kernel(const float* __restrict__ img,
                            const float* __restrict__ mol) {
    const int t = threadIdx.x;
    const int gr = blockIdx.x * 2 + (t >> 7);
    const int c  = t & 127;
    const float* src = (gr < NN) ? (img + (size_t)gr * CC) : (mol + (size_t)(gr - NN) * CC);

    float v = src[c];
    float s = v * v;
    #pragma unroll
    for (int m = 16; m > 0; m >>= 1) s += __shfl_xor_sync(0xffffffffu, s, m);
    __shared__ float red[8];
    if ((t & 31) == 0) red[t >> 5] = s;
    __syncthreads();
    const int rbase = (t >> 7) * 4;
    s = red[rbase] + red[rbase + 1] + red[rbase + 2] + red[rbase + 3];

    const float scale = 3.16227766016837933f / fmaxf(sqrtf(s), 1e-12f);
    const __nv_fp8_e4m3 q(v * scale);
    g_Z[(size_t)gr * CC + c] = *(const uint8_t*)&q;
}

// ---------------------------------------------------------------------------
// Upper-triangular Gram in fp8: 148 persistent CTAs, 16 warps (4x4 warp grid),
// CTA tile 128x128, warp tile 32x32. R9 control flow (proven), with:
//  - A fragments shared across both N-halves (16 ldsm/tile)
//  - f16x2 exp epilogue on non-diagonal tiles (half the MUFU ops)
__global__ __launch_bounds__(NTHR) void gram_kernel() {
    extern __shared__ __align__(256) unsigned char smem[];
    const uint32_t sb = smem_u32(smem);
    const int tid = threadIdx.x;
    const int wid = tid >> 5, lane = tid & 31;
    const int wm = wid >> 2, wn = wid & 3;    // 4x4 warp grid, 32x32 warp tiles

    const int lrow = lane & 15;
    const int lchk = lane >> 4;
    const uint32_t a_off = (uint32_t)((wm * 32 + lrow) * PITCHB + lchk * 16);
    const uint32_t b_off = (uint32_t)((wn * 32 + lrow) * PITCHB + lchk * 16);

    auto load_pair = [&](int n_iter) {
        const int t = blockIdx.x + n_iter * GRIDG;
        if (t < NTILES) {
            int i, j; t2ij(t, i, j);
            const uint32_t slot = sb + (uint32_t)(n_iter % 3) * SLOT_BYTES;
            const uint8_t* srcx = g_Z + (size_t)i * 128 * CC;
            const uint8_t* srcy = g_Z + (size_t)j * 128 * CC;
            #pragma unroll
            for (int l = 0; l < 2; ++l) {
                const int idx = tid + l * NTHR;
                const int row = idx >> 3, c = idx & 7;
                const uint32_t so = (uint32_t)(row * PITCHB + c * 16);
                cp16(slot + so, srcx + row * CC + c * 16);
                cp16(slot + STRIPE_BYTES + so, srcy + row * CC + c * 16);
            }
        }
        CP_COMMIT();
    };

    load_pair(0);
    BAR_ARRIVE();

    int n = 0;
    for (int t = blockIdx.x; t < NTILES; t += GRIDG, ++n) {
        int i, j; t2ij(t, i, j);

        load_pair(n + 1);           // into slot (n+1)%3 (last read finished at iter n-2)
        CP_WAIT(1);                 // own group-n copies complete
        BAR_SYNC();                 // publish all threads' group-n copies; warps past ldsm(n-1)

        const uint32_t xs = sb + (uint32_t)(n % 3) * SLOT_BYTES;
        const uint32_t ys = xs + STRIPE_BYTES;

        // acc flat index f = h*16 + mf*8 + nfp*4 + e   (nf = h*2 + nfp)
        float acc[32];
        #pragma unroll
        for (int f = 0; f < 32; ++f) acc[f] = 0.0f;

        #pragma unroll
        for (int ks = 0; ks < 4; ++ks) {          // K = 128 = 4 x 32
            uint32_t b0[4], b1[4];
            ldsm4(b0, ys + b_off + ks * 32);
            ldsm4(b1, ys + b_off + 16 * PITCHB + ks * 32);
            #pragma unroll
            for (int mf = 0; mf < 2; ++mf) {
                uint32_t a[4];
                ldsm4(a, xs + a_off + mf * 16 * PITCHB + ks * 32);
                mma16832(&acc[mf * 8 + 0],      a, b0[0], b0[2]);
                mma16832(&acc[mf * 8 + 4],      a, b0[1], b0[3]);
                mma16832(&acc[16 + mf * 8 + 0], a, b1[0], b1[2]);
                mma16832(&acc[16 + mf * 8 + 4], a, b1[1], b1[3]);
            }
        }

        BAR_ARRIVE();   // done reading slot n%3

        const bool dmask = (i == j);
        const bool xmask = (j == i + 64);

        if (!(dmask | xmask)) {
            // ================= fast path: f16x2 exp pipeline ================
            uint32_t Rv[2][2] = {{0u, 0u}, {0u, 0u}};   // [mf][b]; lo+hi same row
            uint32_t Cv[4]    = {0u, 0u, 0u, 0u};       // [nf];   lo=col even, hi=col odd

            #pragma unroll
            for (int fp = 0; fp < 16; ++fp) {
                const int f  = fp * 2;
                const int mf = (f >> 3) & 1;
                const int nf = (f >> 4) * 2 + ((f >> 2) & 1);
                const int b  = (f >> 1) & 1;
                const float a0 = fmaf(acc[f],     LOG2E, ESHIFT);
                const float a1 = fmaf(acc[f + 1], LOG2E, ESHIFT);
                const uint32_t ex = ex2_h2(pack_h2(a0, a1));
                Rv[mf][b] = hadd2(Rv[mf][b], ex);
                Cv[nf]    = hadd2(Cv[nf], ex);
            }

            float* dst = ((i < 64) == (j < 64)) ? g_rowS : g_rowX;

            // row sums: reduce over 4 tx lanes, one atomic per (mf,b)
            #pragma unroll
            for (int mf = 0; mf < 2; ++mf)
                #pragma unroll
                for (int b = 0; b < 2; ++b) {
                    uint32_t v = Rv[mf][b];
                    v = hadd2(v, __shfl_xor_sync(0xffffffffu, v, 1));
                    v = hadd2(v, __shfl_xor_sync(0xffffffffu, v, 2));
                    if ((lane & 3) == 0) {
                        const __half2 h = *reinterpret_cast<const __half2*>(&v);
                        atomicAdd(&dst[i * 128 + wm * 32 + mf * 16 + (lane >> 2) + b * 8],
                                  __half2float(h.x) + __half2float(h.y));
                    }
                }

            // col sums (symmetric contribution; i != j on this path)
            #pragma unroll
            for (int nf = 0; nf < 4; ++nf) {
                uint32_t v = Cv[nf];
                v = hadd2(v, __shfl_xor_sync(0xffffffffu, v, 4));
                v = hadd2(v, __shfl_xor_sync(0xffffffffu, v, 8));
                v = hadd2(v, __shfl_xor_sync(0xffffffffu, v, 16));
                if (lane < 4) {
                    const __half2 h = *reinterpret_cast<const __half2*>(&v);
                    atomicAdd(&dst[j * 128 + wn * 32 + nf * 8 + (lane << 1)],     __half2float(h.x));
                    atomicAdd(&dst[j * 128 + wn * 32 + nf * 8 + (lane << 1) + 1], __half2float(h.y));
                }
            }
        } else {
            // ============ slow path (192 tiles): exact f32, diag mask ========
            float rowp[2][2] = {{0, 0}, {0, 0}};
            float colp[4][2] = {{0, 0}, {0, 0}, {0, 0}, {0, 0}};
            float sd = 0.0f;

            #pragma unroll
            for (int f = 0; f < 32; ++f) {
                const float s = acc[f];
                float ex = ex2f(fmaf(s, LOG2E, ESHIFT));
                const int mf = (f >> 3) & 1;
                const int nf = (f >> 4) * 2 + ((f >> 2) & 1);
                const int e  = f & 3;
                const int rl = wm * 32 + mf * 16 + (lane >> 2) + ((e >> 1) << 3);
                const int cl = wn * 32 + nf * 8 + ((lane & 3) << 1) + (e & 1);
                if (rl == cl) { sd += s; ex = 0.0f; }
                rowp[mf][e >> 1] += ex;
                colp[nf][e & 1]  += ex;
            }

            float* dst = ((i < 64) == (j < 64)) ? g_rowS : g_rowX;

            #pragma unroll
            for (int mf = 0; mf < 2; ++mf)
                #pragma unroll
                for (int h = 0; h < 2; ++h) {
                    float v = rowp[mf][h];
                    v += __shfl_xor_sync(0xffffffffu, v, 1);
                    v += __shfl_xor_sync(0xffffffffu, v, 2);
                    if ((lane & 3) == 0)
                        atomicAdd(&dst[i * 128 + wm * 32 + mf * 16 + (lane >> 2) + h * 8], v);
                }

            if (i != j) {
                #pragma unroll
                for (int nf = 0; nf < 4; ++nf)
                    #pragma unroll
                    for (int h = 0; h < 2; ++h) {
                        float v = colp[nf][h];
                        v += __shfl_xor_sync(0xffffffffu, v, 4);
                        v += __shfl_xor_sync(0xffffffffu, v, 8);
                        v += __shfl_xor_sync(0xffffffffu, v, 16);
                        if (lane < 4)
                            atomicAdd(&dst[j * 128 + wn * 32 + nf * 8 + (lane << 1) + h], v);
                    }
            }

            if (xmask) {    // positive-pair logits on this tile's diagonal
                #pragma unroll
                for (int m = 16; m > 0; m >>= 1) sd += __shfl_xor_sync(0xffffffffu, sd, m);
                if (lane == 0) atomicAdd(&g_sumd, (double)sd);
            }
        }
    }
}

// ---------------------------------------------------------------------------
__global__ void logsum_kernel() {
    const int r = blockIdx.x * 256 + threadIdx.x;   // 64 x 256 = 16384
    float l = logf(g_rowS[r]) + logf(g_rowX[r]);
    #pragma unroll
    for (int m = 16; m > 0; m >>= 1) l += __shfl_xor_sync(0xffffffffu, l, m);
    __shared__ float red[8];
    if ((threadIdx.x & 31) == 0) red[threadIdx.x >> 5] = l;
    __syncthreads();
    if (threadIdx.x == 0) {
        float bs = 0.0f;
        #pragma unroll
        for (int w = 0; w < 8; ++w) bs += red[w];
        atomicAdd(&g_sumlog, (double)bs);
    }
}

__global__ void finalize_kernel(float* __restrict__ out) {
    const double invN = 1.0 / (double)NN;
    out[0] = (float)(-g_sumd * invN + 20.0 + 0.5 * g_sumlog * invN);
}

// ---------------------------------------------------------------------------
extern "C" void kernel_launch(void* const* d_in, const int* in_sizes, int n_in,
                              void* d_out, int out_size) {
    const float* img = (const float*)d_in[0];
    const float* mol = (const float*)d_in[1];
    float* out = (float*)d_out;

    cudaFuncSetAttribute(gram_kernel, cudaFuncAttributeMaxDynamicSharedMemorySize, SMEM_TOTAL);

    init_kernel<<<64, 256>>>();
    norm_kernel<<<NROW / 2, 256>>>(img, mol);
    pad_kernel<<<1, 32>>>();                     // aligns gram_kernel into ncu's -s 5 -c 1 slot
    gram_kernel<<<GRIDG, NTHR, SMEM_TOTAL>>>();
    logsum_kernel<<<64, 256>>>();
    finalize_kernel<<<1, 1>>>(out);
}